// round 6
// baseline (speedup 1.0000x reference)
#include <cuda_runtime.h>
#include <cstdint>

#define N_NODES 50000
#define N_EDGES 800000
#define N_GRAPHS 500

// ---------------- scratch (device globals: allocation-free) ----------------
__device__ __align__(16) float g_feat[N_NODES * 128]; // GEMM output (layer feat)
__device__ __align__(16) float g_agg [N_NODES * 128]; // scatter-agg output
__device__ __align__(16) float g_el  [N_NODES * 4];
__device__ __align__(16) float g_er  [N_NODES * 4];
__device__ __align__(16) float g_den [N_NODES * 4];   // softmax denom -> recip
__device__ __align__(16) float g_e   [N_EDGES * 4];   // exp(edge score)
__device__ __align__(16) float g_bn  [256];           // [0:128) sum, [128:256) sumsq
__device__ __align__(16) float g_bnp [256];           // [0:128) scale, [128:256) shift
__device__ __align__(16) float g_hg  [N_GRAPHS * 32]; // pooled graph features
__device__ __align__(16) float g_wsc0[128 * 8];       // folded W*al/W*ar per layer
__device__ __align__(16) float g_wsc1[128 * 8];

__device__ __forceinline__ void red_add_v4(float* p, float4 v) {
    asm volatile("red.global.add.v4.f32 [%0], {%1,%2,%3,%4};"
                 :: "l"(p), "f"(v.x), "f"(v.y), "f"(v.z), "f"(v.w) : "memory");
}
__device__ __forceinline__ void red_add_f(float* p, float v) {
    asm volatile("red.global.add.f32 [%0], %1;" :: "l"(p), "f"(v) : "memory");
}
__device__ __forceinline__ unsigned long long pack2(float w) {
    unsigned long long r;
    asm("mov.b64 %0, {%1, %1};" : "=l"(r) : "r"(__float_as_uint(w)));
    return r;
}
__device__ __forceinline__ void ffma2(unsigned long long& d, unsigned long long a,
                                      unsigned long long b) {
    asm("fma.rn.f32x2 %0, %1, %2, %0;" : "+l"(d) : "l"(a), "l"(b));
}

// ---------------- zero scratch regions (one launch per layer) ----------------
__global__ void k_reset(float4* agg, int na4, float4* den, int nd4,
                        float4* bn, int nb4, float4* hg, int nh4) {
    int i = blockIdx.x * blockDim.x + threadIdx.x;
    float4 z = make_float4(0.f, 0.f, 0.f, 0.f);
    if (i < na4) agg[i] = z;
    if (i < nd4) den[i] = z;
    if (i < nb4) bn[i] = z;
    if (i < nh4) hg[i] = z;
}

// ---------------- fold W with al/ar: Wsc[k][o] (o<4: el heads, o>=4: er) ----
__global__ void k_wsc_all(const float* __restrict__ W0, const float* __restrict__ al0,
                          const float* __restrict__ ar0,
                          const float* __restrict__ W1, const float* __restrict__ al1,
                          const float* __restrict__ ar1) {
    int k = threadIdx.x;
    const float* W  = blockIdx.x ? W1  : W0;
    const float* al = blockIdx.x ? al1 : al0;
    const float* ar = blockIdx.x ? ar1 : ar0;
    float* o = blockIdx.x ? g_wsc1 : g_wsc0;
#pragma unroll
    for (int h = 0; h < 4; h++) {
        float sa = 0.f, sr = 0.f;
#pragma unroll
        for (int d = 0; d < 32; d++) {
            float w = W[k * 128 + h * 32 + d];
            sa = fmaf(w, al[h * 32 + d], sa);
            sr = fmaf(w, ar[h * 32 + d], sr);
        }
        o[k * 8 + h] = sa;
        o[k * 8 + 4 + h] = sr;
    }
}

// ---------------- tiled GEMM 128x128, 16 rows/block, f32x2, fused BN + el/er --
#define GROWS 16
__global__ void __launch_bounds__(128) k_gemm128t(const float* __restrict__ xin,
        const float* __restrict__ W, const float* __restrict__ Wsc, int useBN) {
    __shared__ float xs[128][20];   // [k][r], rows padded 16->20 (10 KB)
    int t = threadIdx.x;
    int row0 = blockIdx.x * GROWS;
    float sc = 1.f, sh = 0.f;
    if (useBN) { sc = g_bnp[t]; sh = g_bnp[128 + t]; }
#pragma unroll
    for (int j = 0; j < GROWS; j++) {
        float v = xin[(row0 + j) * 128 + t];
        if (useBN) v = fmaxf(fmaf(v, sc, sh), 0.f);
        xs[t][j] = v;
    }
    __syncthreads();

    unsigned long long acc[8];
#pragma unroll
    for (int i = 0; i < 8; i++) acc[i] = 0ull;
#pragma unroll 4
    for (int k = 0; k < 128; k++) {
        unsigned long long w2 = pack2(__ldg(&W[k * 128 + t]));
        const ulonglong2* xk = (const ulonglong2*)&xs[k][0];
        ulonglong2 p0 = xk[0], p1 = xk[1], p2 = xk[2], p3 = xk[3];
        ffma2(acc[0], p0.x, w2); ffma2(acc[1], p0.y, w2);
        ffma2(acc[2], p1.x, w2); ffma2(acc[3], p1.y, w2);
        ffma2(acc[4], p2.x, w2); ffma2(acc[5], p2.y, w2);
        ffma2(acc[6], p3.x, w2); ffma2(acc[7], p3.y, w2);
    }
#pragma unroll
    for (int i = 0; i < 8; i++) {
        float2 v = *(float2*)&acc[i];
        g_feat[(row0 + 2 * i) * 128 + t]     = v.x;
        g_feat[(row0 + 2 * i + 1) * 128 + t] = v.y;
    }
    // el/er epilogue: thread t -> row r = t>>3, output o = t&7 (4 el + 4 er heads)
    int r = t >> 3, o = t & 7;
    float a = 0.f;
#pragma unroll 8
    for (int k = 0; k < 128; k++) a = fmaf(xs[k][r], __ldg(&Wsc[k * 8 + o]), a);
    if (o < 4) g_el[(row0 + r) * 4 + o] = a;
    else       g_er[(row0 + r) * 4 + (o - 4)] = a;
}

// ---------------- GEMM 128x32 (layer 2, H=1) with fused BN + el/er -----------
__global__ void k_gemm32(const float* __restrict__ xin, const float* __restrict__ W,
                         const float* __restrict__ al, const float* __restrict__ ar) {
    __shared__ float xs[4][132];
    int t = threadIdx.x;
    int r = t >> 5, c = t & 31;
    int row = blockIdx.x * 4 + r;
#pragma unroll
    for (int j = 0; j < 4; j++) {
        int col = c + 32 * j;
        float v = xin[row * 128 + col];
        v = fmaxf(fmaf(v, g_bnp[col], g_bnp[128 + col]), 0.f);
        xs[r][col] = v;
    }
    __syncthreads();
    float acc = 0.f;
#pragma unroll 16
    for (int k = 0; k < 128; k++) acc = fmaf(xs[r][k], __ldg(&W[k * 32 + c]), acc);
    g_feat[row * 32 + c] = acc;
    float vl = acc * __ldg(&al[c]);
    float vr = acc * __ldg(&ar[c]);
#pragma unroll
    for (int o = 16; o > 0; o >>= 1) {
        vl += __shfl_down_sync(0xffffffffu, vl, o);
        vr += __shfl_down_sync(0xffffffffu, vr, o);
    }
    if (c == 0) { g_el[row] = vl; g_er[row] = vr; }
}

// ---------------- fused edge pass: score + leaky + exp + denom RED (H=4) -----
__global__ void k_edge4(const int* __restrict__ src, const int* __restrict__ dst) {
    int e = blockIdx.x * blockDim.x + threadIdx.x;
    if (e >= N_EDGES) return;
    int s = __ldg(&src[e]), d = __ldg(&dst[e]);
    float4 l = *(const float4*)(g_el + s * 4);
    float4 r = *(const float4*)(g_er + d * 4);
    float4 v;
    v.x = l.x + r.x; v.y = l.y + r.y; v.z = l.z + r.z; v.w = l.w + r.w;
    v.x = v.x > 0.f ? v.x : 0.2f * v.x;  v.y = v.y > 0.f ? v.y : 0.2f * v.y;
    v.z = v.z > 0.f ? v.z : 0.2f * v.z;  v.w = v.w > 0.f ? v.w : 0.2f * v.w;
    v.x = __expf(v.x); v.y = __expf(v.y); v.z = __expf(v.z); v.w = __expf(v.w);
    *(float4*)(g_e + e * 4) = v;
    red_add_v4(g_den + d * 4, v);
}

// ---------------- fused edge pass (H=1) --------------------------------------
__global__ void k_edge1(const int* __restrict__ src, const int* __restrict__ dst) {
    int e = blockIdx.x * blockDim.x + threadIdx.x;
    if (e >= N_EDGES) return;
    int s = __ldg(&src[e]), d = __ldg(&dst[e]);
    float v = g_el[s] + g_er[d];
    v = v > 0.f ? v : 0.2f * v;
    float ex = __expf(v);
    g_e[e] = ex;
    red_add_f(&g_den[d], ex);
}

// ---------------- denominator -> reciprocal ----------------------------------
__global__ void k_invden(int n) {
    int i = blockIdx.x * blockDim.x + threadIdx.x;
    if (i < n) g_den[i] = __frcp_rn(g_den[i]);
}

// ---------------- weighted scatter (H=4, D=32): warp/edge, red.v4 ------------
__global__ void k_eagg128(const int* __restrict__ src, const int* __restrict__ dst) {
    int gt = blockIdx.x * blockDim.x + threadIdx.x;
    int w = gt >> 5;
    if (w >= N_EDGES) return;
    int l = threadIdx.x & 31;
    int s = __ldg(&src[w]), d = __ldg(&dst[w]);
    int h = l >> 3;
    float alpha = __ldg(&g_e[w * 4 + h]) * __ldg(&g_den[d * 4 + h]);
    float4 v = *(const float4*)(g_feat + s * 128 + l * 4);
    v.x *= alpha; v.y *= alpha; v.z *= alpha; v.w *= alpha;
    red_add_v4(g_agg + d * 128 + l * 4, v);
}

// ---------------- weighted scatter (H=1, D=32) -------------------------------
__global__ void k_eagg32(const int* __restrict__ src, const int* __restrict__ dst) {
    int i = blockIdx.x * blockDim.x + threadIdx.x;
    if (i >= N_EDGES * 8) return;
    int e = i >> 3, g = i & 7;
    int s = __ldg(&src[e]), d = __ldg(&dst[e]);
    float alpha = __ldg(&g_e[e]) * __ldg(&g_den[d]);
    float4 v = *(const float4*)(g_feat + s * 32 + g * 4);
    v.x *= alpha; v.y *= alpha; v.z *= alpha; v.w *= alpha;
    red_add_v4(g_agg + d * 32 + g * 4, v);
}

// ---------------- BN stats: column-per-thread register accumulation ----------
__global__ void k_bnstat() {
    int t = threadIdx.x;           // column 0..127
    float s = 0.f, q = 0.f;
    for (int row = blockIdx.x; row < N_NODES; row += gridDim.x) {
        float v = g_agg[row * 128 + t];
        s += v; q = fmaf(v, v, q);
    }
    atomicAdd(&g_bn[t], s);
    atomicAdd(&g_bn[128 + t], q);
}

// ---------------- BN -> affine (scale, shift); bias b cancels under BN -------
__global__ void k_bnprep(const float* __restrict__ gamma, const float* __restrict__ beta) {
    int t = threadIdx.x;
    const float invN = 1.f / (float)N_NODES;
    float mean = g_bn[t] * invN;
    float var  = g_bn[128 + t] * invN - mean * mean;
    float s = gamma[t] * rsqrtf(var + 1e-5f);
    g_bnp[t] = s;
    g_bnp[128 + t] = fmaf(-mean, s, beta[t]);
}

// ---------------- graph sum-pool (adds layer-2 bias per node) ----------------
__global__ void k_pool(const int* __restrict__ gid, const float* __restrict__ b2) {
    int i = blockIdx.x * blockDim.x + threadIdx.x;
    if (i >= N_NODES * 8) return;
    int n = i >> 3, q = i & 7;
    float4 v = *(const float4*)(g_agg + n * 32 + q * 4);
    const float4 b = *(const float4*)(b2 + q * 4);
    v.x += b.x; v.y += b.y; v.z += b.z; v.w += b.w;
    red_add_v4(g_hg + __ldg(&gid[n]) * 32 + q * 4, v);
}

// ---------------- classifier: [500,32] @ [32,10] + bc ------------------------
__global__ void k_cls(const float* __restrict__ Wc, const float* __restrict__ bc,
                      float* __restrict__ out) {
    int i = blockIdx.x * blockDim.x + threadIdx.x;
    if (i >= N_GRAPHS * 10) return;
    int g = i / 10, c = i - g * 10;
    float a = __ldg(&bc[c]);
#pragma unroll
    for (int k = 0; k < 32; k++) a = fmaf(g_hg[g * 32 + k], __ldg(&Wc[k * 10 + c]), a);
    out[i] = a;
}

static inline int divup(int a, int b) { return (a + b - 1) / b; }

extern "C" void kernel_launch(void* const* d_in, const int* in_sizes, int n_in,
                              void* d_out, int out_size) {
    const float* x    = (const float*)d_in[0];
    const int*   src  = (const int*)d_in[1];
    const int*   dst  = (const int*)d_in[2];
    const int*   gid  = (const int*)d_in[3];
    const float* W0   = (const float*)d_in[4];
    const float* al0  = (const float*)d_in[5];
    const float* ar0  = (const float*)d_in[6];
    const float* W1   = (const float*)d_in[8];
    const float* al1  = (const float*)d_in[9];
    const float* ar1  = (const float*)d_in[10];
    const float* W2   = (const float*)d_in[12];
    const float* al2  = (const float*)d_in[13];
    const float* ar2  = (const float*)d_in[14];
    const float* b2   = (const float*)d_in[15];
    const float* g0   = (const float*)d_in[16];
    const float* be0  = (const float*)d_in[17];
    const float* g1   = (const float*)d_in[18];
    const float* be1  = (const float*)d_in[19];
    const float* Wc   = (const float*)d_in[20];
    const float* bc   = (const float*)d_in[21];
    float* out = (float*)d_out;

    void *paggv, *pdenv, *pbnv, *phgv, *pwsc0v, *pwsc1v;
    cudaGetSymbolAddress(&paggv, g_agg);
    cudaGetSymbolAddress(&pdenv, g_den);
    cudaGetSymbolAddress(&pbnv,  g_bn);
    cudaGetSymbolAddress(&phgv,  g_hg);
    cudaGetSymbolAddress(&pwsc0v, g_wsc0);
    cudaGetSymbolAddress(&pwsc1v, g_wsc1);
    float4* pagg = (float4*)paggv;
    float4* pden = (float4*)pdenv;
    float4* pbn  = (float4*)pbnv;
    float4* phg  = (float4*)phgv;
    const float* pagg_f = (const float*)paggv;

    const int B = 256;
    const int NA4 = N_NODES * 128 / 4;   // g_agg float4 count
    const int ND4 = N_NODES * 4 / 4;     // g_den float4 count (H=4)

    k_wsc_all<<<2, 128>>>(W0, al0, ar0, W1, al1, ar1);

    // ---- layer 0 (H=4) ----
    k_gemm128t<<<N_NODES / GROWS, 128>>>(x, W0, (const float*)pwsc0v, 0);
    k_reset<<<divup(NA4, B), B>>>(pagg, NA4, pden, ND4, pbn, 64, phg, 0);
    k_edge4<<<divup(N_EDGES, B), B>>>(src, dst);
    k_invden<<<divup(N_NODES * 4, B), B>>>(N_NODES * 4);
    k_eagg128<<<divup(N_EDGES * 32, B), B>>>(src, dst);
    k_bnstat<<<512, 128>>>();
    k_bnprep<<<1, 128>>>(g0, be0);

    // ---- layer 1 (H=4) ----
    k_gemm128t<<<N_NODES / GROWS, 128>>>(pagg_f, W1, (const float*)pwsc1v, 1);
    k_reset<<<divup(NA4, B), B>>>(pagg, NA4, pden, ND4, pbn, 64, phg, 0);
    k_edge4<<<divup(N_EDGES, B), B>>>(src, dst);
    k_invden<<<divup(N_NODES * 4, B), B>>>(N_NODES * 4);
    k_eagg128<<<divup(N_EDGES * 32, B), B>>>(src, dst);
    k_bnstat<<<512, 128>>>();
    k_bnprep<<<1, 128>>>(g1, be1);

    // ---- layer 2 (H=1, D=32) ----
    k_gemm32<<<N_NODES / 4, 128>>>(pagg_f, W2, al2, ar2);
    k_reset<<<divup(N_NODES * 32 / 4, B), B>>>(pagg, N_NODES * 32 / 4,
                                               pden, N_NODES / 4, pbn, 0,
                                               phg, N_GRAPHS * 32 / 4);
    k_edge1<<<divup(N_EDGES, B), B>>>(src, dst);
    k_invden<<<divup(N_NODES, B), B>>>(N_NODES);
    k_eagg32<<<divup(N_EDGES * 8, B), B>>>(src, dst);

    // ---- pool + classify ----
    k_pool<<<divup(N_NODES * 8, B), B>>>(gid, b2);
    k_cls<<<divup(N_GRAPHS * 10, B), B>>>(Wc, bc, out);
}

// round 9
// speedup vs baseline: 2.1919x; 2.1919x over previous
#include <cuda_runtime.h>
#include <cstdint>

#define N_NODES 50000
#define N_EDGES 800000
#define N_GRAPHS 500

// ---------------- scratch (device globals: allocation-free) ----------------
__device__ __align__(16) float g_feat[N_NODES * 128]; // GEMM output (layer feat)
__device__ __align__(16) float g_agg [N_NODES * 128]; // gather-agg output
__device__ __align__(16) float g_el  [N_NODES * 4];
__device__ __align__(16) float g_er  [N_NODES * 4];
__device__ __align__(16) float g_bn  [256];           // [0:128) sum, [128:256) sumsq
__device__ __align__(16) float g_bnp [256];           // [0:128) scale, [128:256) shift
__device__ __align__(16) float g_hg  [N_GRAPHS * 32]; // pooled graph features
__device__ __align__(16) float g_wsc0[128 * 8];       // folded W*al/W*ar per layer
__device__ __align__(16) float g_wsc1[128 * 8];
// CSR (by destination), rebuilt every launch
__device__ int g_rowptr[N_NODES + 1];
__device__ int g_cursor[N_NODES];
__device__ int g_csrc  [N_EDGES];
__device__ int g_part  [256];
__device__ int g_poff  [256];

__device__ __forceinline__ void red_add_v4(float* p, float4 v) {
    asm volatile("red.global.add.v4.f32 [%0], {%1,%2,%3,%4};"
                 :: "l"(p), "f"(v.x), "f"(v.y), "f"(v.z), "f"(v.w) : "memory");
}
__device__ __forceinline__ unsigned long long pack2(float w) {
    unsigned long long r;
    asm("mov.b64 %0, {%1, %1};" : "=l"(r) : "r"(__float_as_uint(w)));
    return r;
}
__device__ __forceinline__ void ffma2(unsigned long long& d, unsigned long long a,
                                      unsigned long long b) {
    asm("fma.rn.f32x2 %0, %1, %2, %0;" : "+l"(d) : "l"(a), "l"(b));
}

// ---------------- init: zero counters, bn accum, pooled graphs ---------------
__global__ void k_init() {
    int i = blockIdx.x * blockDim.x + threadIdx.x;
    if (i < N_NODES) g_cursor[i] = 0;
    if (i < N_GRAPHS * 32) g_hg[i] = 0.f;
    if (i < 256) g_bn[i] = 0.f;
}

// ---------------- CSR build ---------------------------------------------------
__global__ void k_hist(const int* __restrict__ dst) {
    int e = blockIdx.x * blockDim.x + threadIdx.x;
    if (e < N_EDGES) atomicAdd(&g_cursor[__ldg(&dst[e])], 1);
}
__global__ void k_scanA() {
    __shared__ int sh[256];
    int t = threadIdx.x, i = blockIdx.x * 256 + t;
    int v = (i < N_NODES) ? g_cursor[i] : 0;
    sh[t] = v; __syncthreads();
    for (int off = 1; off < 256; off <<= 1) {
        int x = (t >= off) ? sh[t - off] : 0;
        __syncthreads();
        sh[t] += x;
        __syncthreads();
    }
    if (i < N_NODES) g_rowptr[i] = sh[t] - v;   // block-local exclusive
    if (t == 255) g_part[blockIdx.x] = sh[255];
}
__global__ void k_scanB() {
    __shared__ int sh[256];
    int t = threadIdx.x;
    int v = (t < 196) ? g_part[t] : 0;
    sh[t] = v; __syncthreads();
    for (int off = 1; off < 256; off <<= 1) {
        int x = (t >= off) ? sh[t - off] : 0;
        __syncthreads();
        sh[t] += x;
        __syncthreads();
    }
    g_poff[t] = sh[t] - v;                      // exclusive block offsets
}
__global__ void k_scanC() {
    int i = blockIdx.x * 256 + threadIdx.x;
    if (i < N_NODES) {
        int r = g_rowptr[i] + g_poff[blockIdx.x];
        g_rowptr[i] = r;
        g_cursor[i] = r;
    }
    if (i == 0) g_rowptr[N_NODES] = N_EDGES;
}
__global__ void k_bin(const int* __restrict__ src, const int* __restrict__ dst) {
    int e = blockIdx.x * blockDim.x + threadIdx.x;
    if (e >= N_EDGES) return;
    int pos = atomicAdd(&g_cursor[__ldg(&dst[e])], 1);
    g_csrc[pos] = __ldg(&src[e]);
}

// ---------------- fold W with al/ar: Wsc[k][o] (o<4: el heads, o>=4: er) -----
__global__ void k_wsc_all(const float* __restrict__ W0, const float* __restrict__ al0,
                          const float* __restrict__ ar0,
                          const float* __restrict__ W1, const float* __restrict__ al1,
                          const float* __restrict__ ar1) {
    int k = threadIdx.x;
    const float* W  = blockIdx.x ? W1  : W0;
    const float* al = blockIdx.x ? al1 : al0;
    const float* ar = blockIdx.x ? ar1 : ar0;
    float* o = blockIdx.x ? g_wsc1 : g_wsc0;
#pragma unroll
    for (int h = 0; h < 4; h++) {
        float sa = 0.f, sr = 0.f;
#pragma unroll
        for (int d = 0; d < 32; d++) {
            float w = W[k * 128 + h * 32 + d];
            sa = fmaf(w, al[h * 32 + d], sa);
            sr = fmaf(w, ar[h * 32 + d], sr);
        }
        o[k * 8 + h] = sa;
        o[k * 8 + 4 + h] = sr;
    }
}

// ---------------- tiled GEMM 128x128, 16 rows/block, f32x2, fused BN + el/er --
#define GROWS 16
__global__ void __launch_bounds__(128) k_gemm128t(const float* __restrict__ xin,
        const float* __restrict__ W, const float* __restrict__ Wsc, int useBN) {
    __shared__ float xs[128][20];
    int t = threadIdx.x;
    int row0 = blockIdx.x * GROWS;
    float sc = 1.f, sh = 0.f;
    if (useBN) { sc = g_bnp[t]; sh = g_bnp[128 + t]; }
#pragma unroll
    for (int j = 0; j < GROWS; j++) {
        float v = xin[(row0 + j) * 128 + t];
        if (useBN) v = fmaxf(fmaf(v, sc, sh), 0.f);
        xs[t][j] = v;
    }
    __syncthreads();

    unsigned long long acc[8];
#pragma unroll
    for (int i = 0; i < 8; i++) acc[i] = 0ull;
#pragma unroll 4
    for (int k = 0; k < 128; k++) {
        unsigned long long w2 = pack2(__ldg(&W[k * 128 + t]));
        const ulonglong2* xk = (const ulonglong2*)&xs[k][0];
        ulonglong2 p0 = xk[0], p1 = xk[1], p2 = xk[2], p3 = xk[3];
        ffma2(acc[0], p0.x, w2); ffma2(acc[1], p0.y, w2);
        ffma2(acc[2], p1.x, w2); ffma2(acc[3], p1.y, w2);
        ffma2(acc[4], p2.x, w2); ffma2(acc[5], p2.y, w2);
        ffma2(acc[6], p3.x, w2); ffma2(acc[7], p3.y, w2);
    }
#pragma unroll
    for (int i = 0; i < 8; i++) {
        float2 v = *(float2*)&acc[i];
        g_feat[(row0 + 2 * i) * 128 + t]     = v.x;
        g_feat[(row0 + 2 * i + 1) * 128 + t] = v.y;
    }
    int r = t >> 3, o = t & 7;
    float a = 0.f;
#pragma unroll 8
    for (int k = 0; k < 128; k++) a = fmaf(xs[k][r], __ldg(&Wsc[k * 8 + o]), a);
    if (o < 4) g_el[(row0 + r) * 4 + o] = a;
    else       g_er[(row0 + r) * 4 + (o - 4)] = a;
}

// ---------------- GEMM 128x32 (layer 2, H=1) with fused BN + el/er -----------
__global__ void k_gemm32(const float* __restrict__ xin, const float* __restrict__ W,
                         const float* __restrict__ al, const float* __restrict__ ar) {
    __shared__ float xs[4][132];
    int t = threadIdx.x;
    int r = t >> 5, c = t & 31;
    int row = blockIdx.x * 4 + r;
#pragma unroll
    for (int j = 0; j < 4; j++) {
        int col = c + 32 * j;
        float v = xin[row * 128 + col];
        v = fmaxf(fmaf(v, g_bnp[col], g_bnp[128 + col]), 0.f);
        xs[r][col] = v;
    }
    __syncthreads();
    float acc = 0.f;
#pragma unroll 16
    for (int k = 0; k < 128; k++) acc = fmaf(xs[r][k], __ldg(&W[k * 32 + c]), acc);
    g_feat[row * 32 + c] = acc;
    float vl = acc * __ldg(&al[c]);
    float vr = acc * __ldg(&ar[c]);
#pragma unroll
    for (int o = 16; o > 0; o >>= 1) {
        vl += __shfl_down_sync(0xffffffffu, vl, o);
        vr += __shfl_down_sync(0xffffffffu, vr, o);
    }
    if (c == 0) { g_el[row] = vl; g_er[row] = vr; }
}

// ---------------- fused GAT edge stage, CSR gather (H=4, D=32) ---------------
// One warp per dst node: score + leaky + exp + softmax + weighted sum, all in
// registers; single coalesced 512B row write. No atomics, no scratch passes.
__global__ void __launch_bounds__(256) k_gat4() {
    int w = (blockIdx.x * blockDim.x + threadIdx.x) >> 5;
    if (w >= N_NODES) return;
    int l = threadIdx.x & 31;
    int h = l >> 3;
    int start = __ldg(&g_rowptr[w]), end = __ldg(&g_rowptr[w + 1]);
    float4 acc = make_float4(0.f, 0.f, 0.f, 0.f);
    if (start < end) {
        float er = __ldg(&g_er[w * 4 + h]);
        float den = 0.f;
        for (int base = start; base < end; base += 32) {
            int idx = base + l;
            int sl = __ldg(&g_csrc[idx < end ? idx : end - 1]);
            int m = min(32, end - base);
            int j = 0;
            for (; j + 1 < m; j += 2) {
                int s0 = __shfl_sync(0xffffffffu, sl, j);
                int s1 = __shfl_sync(0xffffffffu, sl, j + 1);
                float e0 = __ldg(&g_el[s0 * 4 + h]);
                float e1 = __ldg(&g_el[s1 * 4 + h]);
                float4 f0 = *(const float4*)(g_feat + s0 * 128 + l * 4);
                float4 f1 = *(const float4*)(g_feat + s1 * 128 + l * 4);
                e0 += er; e0 = e0 > 0.f ? e0 : 0.2f * e0; float x0 = __expf(e0);
                e1 += er; e1 = e1 > 0.f ? e1 : 0.2f * e1; float x1 = __expf(e1);
                den += x0 + x1;
                acc.x = fmaf(x0, f0.x, fmaf(x1, f1.x, acc.x));
                acc.y = fmaf(x0, f0.y, fmaf(x1, f1.y, acc.y));
                acc.z = fmaf(x0, f0.z, fmaf(x1, f1.z, acc.z));
                acc.w = fmaf(x0, f0.w, fmaf(x1, f1.w, acc.w));
            }
            if (j < m) {
                int s0 = __shfl_sync(0xffffffffu, sl, j);
                float e0 = __ldg(&g_el[s0 * 4 + h]) + er;
                e0 = e0 > 0.f ? e0 : 0.2f * e0; float x0 = __expf(e0);
                float4 f0 = *(const float4*)(g_feat + s0 * 128 + l * 4);
                den += x0;
                acc.x = fmaf(x0, f0.x, acc.x);
                acc.y = fmaf(x0, f0.y, acc.y);
                acc.z = fmaf(x0, f0.z, acc.z);
                acc.w = fmaf(x0, f0.w, acc.w);
            }
        }
        float rd = __frcp_rn(den);
        acc.x *= rd; acc.y *= rd; acc.z *= rd; acc.w *= rd;
    }
    *(float4*)(g_agg + w * 128 + l * 4) = acc;
}

// ---------------- fused GAT stage layer 2 (H=1, D=32) + graph pooling --------
// 8 lanes per dst node (4 dsts per warp); epilogue REDs straight into g_hg.
__global__ void __launch_bounds__(256) k_gat1(const int* __restrict__ gid,
                                              const float* __restrict__ b2) {
    int d = blockIdx.x * 32 + (threadIdx.x >> 3);
    if (d >= N_NODES) return;
    int g = threadIdx.x & 7;
    int start = __ldg(&g_rowptr[d]), end = __ldg(&g_rowptr[d + 1]);
    float4 acc = make_float4(0.f, 0.f, 0.f, 0.f);
    if (start < end) {
        float er = __ldg(&g_er[d]);
        float den = 0.f;
        int j = start;
        for (; j + 1 < end; j += 2) {
            int s0 = __ldg(&g_csrc[j]);
            int s1 = __ldg(&g_csrc[j + 1]);
            float e0 = __ldg(&g_el[s0]) + er;
            float e1 = __ldg(&g_el[s1]) + er;
            float4 f0 = *(const float4*)(g_feat + s0 * 32 + g * 4);
            float4 f1 = *(const float4*)(g_feat + s1 * 32 + g * 4);
            e0 = e0 > 0.f ? e0 : 0.2f * e0; float x0 = __expf(e0);
            e1 = e1 > 0.f ? e1 : 0.2f * e1; float x1 = __expf(e1);
            den += x0 + x1;
            acc.x = fmaf(x0, f0.x, fmaf(x1, f1.x, acc.x));
            acc.y = fmaf(x0, f0.y, fmaf(x1, f1.y, acc.y));
            acc.z = fmaf(x0, f0.z, fmaf(x1, f1.z, acc.z));
            acc.w = fmaf(x0, f0.w, fmaf(x1, f1.w, acc.w));
        }
        if (j < end) {
            int s0 = __ldg(&g_csrc[j]);
            float e0 = __ldg(&g_el[s0]) + er;
            e0 = e0 > 0.f ? e0 : 0.2f * e0; float x0 = __expf(e0);
            float4 f0 = *(const float4*)(g_feat + s0 * 32 + g * 4);
            den += x0;
            acc.x = fmaf(x0, f0.x, acc.x);
            acc.y = fmaf(x0, f0.y, acc.y);
            acc.z = fmaf(x0, f0.z, acc.z);
            acc.w = fmaf(x0, f0.w, acc.w);
        }
        float rd = __frcp_rn(den);
        acc.x *= rd; acc.y *= rd; acc.z *= rd; acc.w *= rd;
    }
    float4 b = __ldg((const float4*)b2 + g);
    acc.x += b.x; acc.y += b.y; acc.z += b.z; acc.w += b.w;
    red_add_v4(g_hg + __ldg(&gid[d]) * 32 + g * 4, acc);
}

// ---------------- BN stats: column-per-thread register accumulation ----------
__global__ void k_bnstat() {
    int t = threadIdx.x;
    float s = 0.f, q = 0.f;
    for (int row = blockIdx.x; row < N_NODES; row += gridDim.x) {
        float v = g_agg[row * 128 + t];
        s += v; q = fmaf(v, v, q);
    }
    atomicAdd(&g_bn[t], s);
    atomicAdd(&g_bn[128 + t], q);
}

// ---------------- BN -> affine (scale, shift); re-zeroes g_bn for next layer -
__global__ void k_bnprep(const float* __restrict__ gamma, const float* __restrict__ beta) {
    int t = threadIdx.x;
    const float invN = 1.f / (float)N_NODES;
    float mean = g_bn[t] * invN;
    float var  = g_bn[128 + t] * invN - mean * mean;
    float s = gamma[t] * rsqrtf(var + 1e-5f);
    g_bnp[t] = s;
    g_bnp[128 + t] = fmaf(-mean, s, beta[t]);
    g_bn[t] = 0.f;
    g_bn[128 + t] = 0.f;
}

// ---------------- classifier: [500,32] @ [32,10] + bc ------------------------
__global__ void k_cls(const float* __restrict__ Wc, const float* __restrict__ bc,
                      float* __restrict__ out) {
    int i = blockIdx.x * blockDim.x + threadIdx.x;
    if (i >= N_GRAPHS * 10) return;
    int g = i / 10, c = i - g * 10;
    float a = __ldg(&bc[c]);
#pragma unroll
    for (int k = 0; k < 32; k++) a = fmaf(g_hg[g * 32 + k], __ldg(&Wc[k * 10 + c]), a);
    out[i] = a;
}

static inline int divup(int a, int b) { return (a + b - 1) / b; }

extern "C" void kernel_launch(void* const* d_in, const int* in_sizes, int n_in,
                              void* d_out, int out_size) {
    const float* x    = (const float*)d_in[0];
    const int*   src  = (const int*)d_in[1];
    const int*   dst  = (const int*)d_in[2];
    const int*   gid  = (const int*)d_in[3];
    const float* W0   = (const float*)d_in[4];
    const float* al0  = (const float*)d_in[5];
    const float* ar0  = (const float*)d_in[6];
    const float* W1   = (const float*)d_in[8];
    const float* al1  = (const float*)d_in[9];
    const float* ar1  = (const float*)d_in[10];
    const float* W2   = (const float*)d_in[12];
    const float* al2  = (const float*)d_in[13];
    const float* ar2  = (const float*)d_in[14];
    const float* b2   = (const float*)d_in[15];
    const float* g0   = (const float*)d_in[16];
    const float* be0  = (const float*)d_in[17];
    const float* g1   = (const float*)d_in[18];
    const float* be1  = (const float*)d_in[19];
    const float* Wc   = (const float*)d_in[20];
    const float* bc   = (const float*)d_in[21];
    float* out = (float*)d_out;

    void *paggv, *pwsc0v, *pwsc1v;
    cudaGetSymbolAddress(&paggv, g_agg);
    cudaGetSymbolAddress(&pwsc0v, g_wsc0);
    cudaGetSymbolAddress(&pwsc1v, g_wsc1);
    const float* pagg_f = (const float*)paggv;

    const int B = 256;
    const int NB_N = divup(N_NODES, B);   // 196
    const int NB_E = divup(N_EDGES, B);

    // ---- CSR build (shared by all 3 layers) ----
    k_init<<<NB_N, B>>>();
    k_hist<<<NB_E, B>>>(dst);
    k_scanA<<<NB_N, B>>>();
    k_scanB<<<1, B>>>();
    k_scanC<<<NB_N, B>>>();
    k_bin<<<NB_E, B>>>(src, dst);
    k_wsc_all<<<2, 128>>>(W0, al0, ar0, W1, al1, ar1);

    // ---- layer 0 (H=4) ----
    k_gemm128t<<<N_NODES / GROWS, 128>>>(x, W0, (const float*)pwsc0v, 0);
    k_gat4<<<divup(N_NODES * 32, B), B>>>();
    k_bnstat<<<512, 128>>>();
    k_bnprep<<<1, 128>>>(g0, be0);

    // ---- layer 1 (H=4) ----
    k_gemm128t<<<N_NODES / GROWS, 128>>>(pagg_f, W1, (const float*)pwsc1v, 1);
    k_gat4<<<divup(N_NODES * 32, B), B>>>();
    k_bnstat<<<512, 128>>>();
    k_bnprep<<<1, 128>>>(g1, be1);

    // ---- layer 2 (H=1, D=32) + fused pooling ----
    k_gemm32<<<N_NODES / 4, 128>>>(pagg_f, W2, al2, ar2);
    k_gat1<<<divup(N_NODES, 32), B>>>(gid, b2);

    // ---- classify ----
    k_cls<<<divup(N_GRAPHS * 10, B), B>>>(Wc, bc, out);
}